// round 1
// baseline (speedup 1.0000x reference)
#include <cuda_runtime.h>

// ---------------- problem constants ----------------
#define BU 8
#define NTOK 320            // v*w = 5*64

// scratch (global device arrays; allocation-free per harness rules)
__device__ float g_X [8*40*5*64*64];   // attention+Wc output, conv1-input layout [b][c8*5+v][ar][h][w]
__device__ float g_Y1[8*64*5*64*64];   // conv1 output [b][c][ar][h][w]

// ---------------- attention kernel smem layout (floats) ----------------
#define PS_STRIDE 324
#define SM_QKV   (64*PS_STRIDE)          // 20736  (region 0: Bs[64][320] then P[64][324])
#define SM_W     (SM_QKV + 56*320)       // 38656
#define SM_RINV  (SM_W + 64*96)          // 44800
#define ATTN_SMEM_FLOATS (SM_RINV + 64)  // 44864
#define ATTN_SMEM_BYTES  (ATTN_SMEM_FLOATS*4)

__global__ __launch_bounds__(512)
void attn_kernel(const float* __restrict__ buffer,
                 const float* __restrict__ Wq, const float* __restrict__ Wk,
                 const float* __restrict__ Wv, const float* __restrict__ Wc)
{
    extern __shared__ float sm[];
    float* Bs   = sm;             // [64][320], c-major, n = v*64+w
    float* Ps   = sm;             // [64][PS_STRIDE], overlays Bs after phase A
    float* QKV  = sm + SM_QKV;    // rows 0-7 Q, 8-15 K, 16-55 V ; [56][320]
    float* Wsm  = sm + SM_W;      // [c][96]  (oc: 0-7 Wq, 8-15 Wk, 16-55 Wv, 56-95 Wc)
    float* rinv = sm + SM_RINV;   // [64] per-row 1/sum for current tile

    const int h    = blockIdx.x;
    const int b    = blockIdx.y;
    const int t    = threadIdx.x;
    const int lane = t & 31;
    const int wid  = t >> 5;      // 16 warps

    // ---- load weights to smem (transposed, broadcast-friendly) ----
    for (int idx = t; idx < 96*64; idx += 512) {
        int oc = idx >> 6, c = idx & 63;
        float v;
        if      (oc <  8) v = Wq[(oc      )*64 + c];
        else if (oc < 16) v = Wk[(oc -  8)*64 + c];
        else if (oc < 56) v = Wv[(oc - 16)*64 + c];
        else              v = Wc[(oc - 56)*64 + c];
        Wsm[c*96 + oc] = v;
    }
    // ---- load buffer slice Bs[c][v*64+w] (float4, coalesced) ----
    for (int f = t; f < 5120; f += 512) {
        int r  = f >> 4;          // c*5 + v
        int w4 = f & 15;
        int c = r / 5, v = r % 5;
        float4 val = *(const float4*)(buffer + (((size_t)(b*64 + c)*5 + v)*4096 + h*64 + w4*4));
        *(float4*)(Bs + c*320 + v*64 + w4*4) = val;
    }
    __syncthreads();

    // ---- Phase A: [96 x 64] x [64 x 320]: Q,K,V to smem, Wc-out to g_X ----
    {
        const int ocb = wid * 6;              // 16 warps * 6 oc = 96
        float acc[6][10];
        #pragma unroll
        for (int i = 0; i < 6; i++)
            #pragma unroll
            for (int j = 0; j < 10; j++) acc[i][j] = 0.f;

        for (int c = 0; c < 64; c++) {
            float wr[6];
            #pragma unroll
            for (int i = 0; i < 6; i++) wr[i] = Wsm[c*96 + ocb + i];
            #pragma unroll
            for (int j = 0; j < 10; j++) {
                float bv = Bs[c*320 + lane + 32*j];
                #pragma unroll
                for (int i = 0; i < 6; i++) acc[i][j] += wr[i]*bv;
            }
        }
        #pragma unroll
        for (int i = 0; i < 6; i++) {
            int oc = ocb + i;
            #pragma unroll
            for (int j = 0; j < 10; j++) {
                int n = lane + 32*j;
                if (oc < 56) {
                    QKV[oc*320 + n] = acc[i][j];
                } else {
                    int cc = oc - 56;                    // attention out-channel = c8*5 + ar
                    int c8 = cc / 5, ar = cc % 5;
                    int v = n >> 6, w = n & 63;
                    g_X[((((size_t)b*40 + c8*5 + v)*5 + ar)*64 + h)*64 + w] = acc[i][j];
                }
            }
        }
    }
    __syncthreads();

    // ---- Phase B: 5 tiles of 64 rows ----
    for (int tile = 0; tile < 5; tile++) {
        const int m0 = tile * 64;

        // B1: scores (inner dim 8) + softmax -> Ps (unnormalized exp), rinv
        {
            float q[4][8];
            #pragma unroll
            for (int mi = 0; mi < 4; mi++)
                #pragma unroll
                for (int d = 0; d < 8; d++)
                    q[mi][d] = QKV[d*320 + m0 + wid*4 + mi];

            float s[4][10];
            #pragma unroll
            for (int j = 0; j < 10; j++) {
                int n = lane + 32*j;
                float kv[8];
                #pragma unroll
                for (int d = 0; d < 8; d++) kv[d] = QKV[(8+d)*320 + n];
                #pragma unroll
                for (int mi = 0; mi < 4; mi++) {
                    float a = 0.f;
                    #pragma unroll
                    for (int d = 0; d < 8; d++) a += q[mi][d]*kv[d];
                    s[mi][j] = a;
                }
            }
            #pragma unroll
            for (int mi = 0; mi < 4; mi++) {
                float mx = s[mi][0];
                #pragma unroll
                for (int j = 1; j < 10; j++) mx = fmaxf(mx, s[mi][j]);
                #pragma unroll
                for (int o = 16; o; o >>= 1) mx = fmaxf(mx, __shfl_xor_sync(0xffffffffu, mx, o));
                float sum = 0.f;
                #pragma unroll
                for (int j = 0; j < 10; j++) { float e = __expf(s[mi][j] - mx); s[mi][j] = e; sum += e; }
                #pragma unroll
                for (int o = 16; o; o >>= 1) sum += __shfl_xor_sync(0xffffffffu, sum, o);
                int r = wid*4 + mi;
                #pragma unroll
                for (int j = 0; j < 10; j++) Ps[r*PS_STRIDE + lane + 32*j] = s[mi][j];
                if (lane == 0) rinv[r] = 1.0f / sum;
            }
        }
        __syncthreads();

        // B2: O[64][40] = P[64][320] * V^T ; subgroup of 8 lanes per row
        {
            const int sg = lane >> 3, l8 = lane & 7;
            const int r  = wid*4 + sg;          // tile-local row
            float acc[40];
            #pragma unroll
            for (int oc = 0; oc < 40; oc++) acc[oc] = 0.f;

            const float* prow = Ps + r*PS_STRIDE;
            const float* vbase = QKV + 16*320;
            for (int jj = 0; jj < 40; jj++) {
                int n = jj*8 + l8;
                float p = prow[n];
                const float* vp = vbase + n;
                #pragma unroll
                for (int oc = 0; oc < 40; oc++) acc[oc] += p * vp[oc*320];
            }
            #pragma unroll
            for (int oc = 0; oc < 40; oc++) {
                float a = acc[oc];
                a += __shfl_xor_sync(0xffffffffu, a, 1);
                a += __shfl_xor_sync(0xffffffffu, a, 2);
                a += __shfl_xor_sync(0xffffffffu, a, 4);
                acc[oc] = a;
            }
            float scale = rinv[r];
            int m_g = m0 + r;
            int v = m_g >> 6, w = m_g & 63;
            // lane l8 writes oc = l8*5 + q2  ->  c8 = l8, ar = q2
            #pragma unroll
            for (int q2 = 0; q2 < 5; q2++) {
                int oc = l8*5 + q2;
                size_t idx = ((((size_t)b*40 + l8*5 + v)*5 + q2)*64 + h)*64 + w;
                g_X[idx] += scale * acc[oc];
            }
        }
        __syncthreads();
    }
}

// ---------------- conv1: [64oc] x [40ci x 7kw] over W, + ReLU ----------------
#define C1_WS_OFF 2880                       // Xs[40][72]
#define C1_SMEM_FLOATS (C1_WS_OFF + 280*65)  // 21080
#define C1_SMEM_BYTES  (C1_SMEM_FLOATS*4)

__global__ __launch_bounds__(256)
void conv1_kernel(const float* __restrict__ W1)
{
    extern __shared__ float sm[];
    float* Xs = sm;               // [ci][72], data at [ci][3+w], pads zeroed
    float* Ws = sm + C1_WS_OFF;   // [(ci*7+kw)*65 + oc]
    const int h = blockIdx.x, d = blockIdx.y, b = blockIdx.z;
    const int t = threadIdx.x, lane = t & 31;
    const int ocb = (t >> 5) * 8;

    // zero pad columns only (indices 0..2 and 64+3..64+5 -> 67..69)
    for (int idx = t; idx < 240; idx += 256) {
        int ci = idx / 6, p = idx % 6;
        Xs[ci*72 + (p < 3 ? p : 64 + p)] = 0.f;
    }
    // fill X rows
    for (int idx = t; idx < 40*64; idx += 256) {
        int ci = idx >> 6, w = idx & 63;
        Xs[ci*72 + 3 + w] = g_X[(((size_t)b*40 + ci)*5 + d)*4096 + h*64 + w];
    }
    // weights: LDG-coalesced, STS conflict-free (stride 65)
    for (int idx = t; idx < 64*280; idx += 256) {
        int oc = idx / 280, r = idx % 280;
        Ws[r*65 + oc] = W1[idx];
    }
    __syncthreads();

    float acc0[8], acc1[8];
    #pragma unroll
    for (int i = 0; i < 8; i++) { acc0[i] = 0.f; acc1[i] = 0.f; }

    for (int ci = 0; ci < 40; ci++) {
        #pragma unroll
        for (int kw = 0; kw < 7; kw++) {
            float x0 = Xs[ci*72 + lane + kw];
            float x1 = Xs[ci*72 + 32 + lane + kw];
            const float* wp = Ws + (ci*7+kw)*65 + ocb;
            #pragma unroll
            for (int i = 0; i < 8; i++) { float wv = wp[i]; acc0[i] += wv*x0; acc1[i] += wv*x1; }
        }
    }
    size_t obase = (((size_t)b*64 + ocb)*5 + d)*4096 + h*64;
    #pragma unroll
    for (int i = 0; i < 8; i++) {
        g_Y1[obase + (size_t)i*5*4096 + lane]      = fmaxf(acc0[i], 0.f);
        g_Y1[obase + (size_t)i*5*4096 + 32 + lane] = fmaxf(acc1[i], 0.f);
    }
}

// ---------------- conv2: [64oc] x [64c x 7kd] over D(=5), + ReLU ----------------
#define C2_WS_OFF 20480                       // Ys[64][5][64]
#define C2_SMEM_FLOATS (C2_WS_OFF + 448*65)   // 49600
#define C2_SMEM_BYTES  (C2_SMEM_FLOATS*4)

__global__ __launch_bounds__(512)
void conv2_kernel(const float* __restrict__ W2, float* __restrict__ out)
{
    extern __shared__ float sm[];
    float* Ys = sm;               // [(c*5+d)*64 + w]
    float* Ws = sm + C2_WS_OFF;   // [(c*7+kd)*65 + oc]
    const int h = blockIdx.x, b = blockIdx.y;
    const int t = threadIdx.x;
    const int oc = t >> 3, wg = t & 7;

    for (int f = t; f < 5120; f += 512) {
        int r = f >> 4, w4 = f & 15;
        int c = r / 5, d = r % 5;
        *(float4*)(Ys + r*64 + w4*4) =
            *(const float4*)(g_Y1 + (((size_t)b*64 + c)*5 + d)*4096 + h*64 + w4*4);
    }
    for (int idx = t; idx < 64*448; idx += 512) {
        int o = idx / 448, r = idx % 448;
        Ws[r*65 + o] = W2[idx];
    }
    __syncthreads();

    float acc[5][8];
    #pragma unroll
    for (int d = 0; d < 5; d++)
        #pragma unroll
        for (int j = 0; j < 8; j++) acc[d][j] = 0.f;

    for (int c = 0; c < 64; c++) {
        float wr[7];
        #pragma unroll
        for (int kd = 0; kd < 7; kd++) wr[kd] = Ws[(c*7+kd)*65 + oc];
        #pragma unroll
        for (int dp = 0; dp < 5; dp++) {
            const float* yp = Ys + (c*5+dp)*64 + wg*8;
            float4 ya = *(const float4*)yp;
            float4 yb = *(const float4*)(yp + 4);
            float y[8] = {ya.x, ya.y, ya.z, ya.w, yb.x, yb.y, yb.z, yb.w};
            #pragma unroll
            for (int d = 0; d < 5; d++) {
                int kd = dp - d + 3;
                if (kd < 0 || kd > 6) continue;     // compile-time pruned
                float wv = wr[kd];
                #pragma unroll
                for (int j = 0; j < 8; j++) acc[d][j] += wv*y[j];
            }
        }
    }
    #pragma unroll
    for (int d = 0; d < 5; d++) {
        size_t idx = (((size_t)b*64 + oc)*5 + d)*4096 + h*64 + wg*8;
        float4 o0, o1;
        o0.x = fmaxf(acc[d][0], 0.f); o0.y = fmaxf(acc[d][1], 0.f);
        o0.z = fmaxf(acc[d][2], 0.f); o0.w = fmaxf(acc[d][3], 0.f);
        o1.x = fmaxf(acc[d][4], 0.f); o1.y = fmaxf(acc[d][5], 0.f);
        o1.z = fmaxf(acc[d][6], 0.f); o1.w = fmaxf(acc[d][7], 0.f);
        *(float4*)(out + idx)     = o0;
        *(float4*)(out + idx + 4) = o1;
    }
}

// ---------------- launch ----------------
extern "C" void kernel_launch(void* const* d_in, const int* in_sizes, int n_in,
                              void* d_out, int out_size)
{
    const float* buffer = (const float*)d_in[0];
    const float* Wq = (const float*)d_in[1];
    const float* Wk = (const float*)d_in[2];
    const float* Wv = (const float*)d_in[3];
    const float* Wc = (const float*)d_in[4];
    const float* W1 = (const float*)d_in[5];
    const float* W2 = (const float*)d_in[6];
    float* out = (float*)d_out;

    cudaFuncSetAttribute(attn_kernel,  cudaFuncAttributeMaxDynamicSharedMemorySize, ATTN_SMEM_BYTES);
    cudaFuncSetAttribute(conv1_kernel, cudaFuncAttributeMaxDynamicSharedMemorySize, C1_SMEM_BYTES);
    cudaFuncSetAttribute(conv2_kernel, cudaFuncAttributeMaxDynamicSharedMemorySize, C2_SMEM_BYTES);

    attn_kernel <<<dim3(64, 8),    512, ATTN_SMEM_BYTES>>>(buffer, Wq, Wk, Wv, Wc);
    conv1_kernel<<<dim3(64, 5, 8), 256, C1_SMEM_BYTES>>>(W1);
    conv2_kernel<<<dim3(64, 8),    512, C2_SMEM_BYTES>>>(W2, out);
}

// round 2
// speedup vs baseline: 1.0008x; 1.0008x over previous
#include <cuda_runtime.h>

// ---------------- problem constants ----------------
#define BU 8
#define NTOK 320            // v*w = 5*64

// scratch (global device arrays; allocation-free per harness rules)
__device__ float g_X [8*40*5*64*64];   // attention+Wc output, conv1-input layout [b][c8*5+v][ar][h][w]
__device__ float g_Y1[8*64*5*64*64];   // conv1 output [b][c][ar][h][w]

// ---------------- attention kernel smem layout (floats) ----------------
#define PS_STRIDE 324
#define SM_QKV   (64*PS_STRIDE)          // 20736  (region 0: Bs[64][320] then P[64][324])
#define SM_W     (SM_QKV + 56*320)       // 38656
#define SM_RINV  (SM_W + 64*96)          // 44800
#define ATTN_SMEM_FLOATS (SM_RINV + 64)  // 44864
#define ATTN_SMEM_BYTES  (ATTN_SMEM_FLOATS*4)

__global__ __launch_bounds__(512)
void attn_kernel(const float* __restrict__ buffer,
                 const float* __restrict__ Wq, const float* __restrict__ Wk,
                 const float* __restrict__ Wv, const float* __restrict__ Wc)
{
    extern __shared__ float sm[];
    float* Bs   = sm;             // [64][320], c-major, n = v*64+w
    float* Ps   = sm;             // [64][PS_STRIDE], overlays Bs after phase A
    float* QKV  = sm + SM_QKV;    // rows 0-7 Q, 8-15 K, 16-55 V ; [56][320]
    float* Wsm  = sm + SM_W;      // [c][96]  (oc: 0-7 Wq, 8-15 Wk, 16-55 Wv, 56-95 Wc)
    float* rinv = sm + SM_RINV;   // [64] per-row 1/sum for current tile

    const int h    = blockIdx.x;
    const int b    = blockIdx.y;
    const int t    = threadIdx.x;
    const int lane = t & 31;
    const int wid  = t >> 5;      // 16 warps

    // ---- load weights to smem (transposed, broadcast-friendly) ----
    for (int idx = t; idx < 96*64; idx += 512) {
        int oc = idx >> 6, c = idx & 63;
        float v;
        if      (oc <  8) v = Wq[(oc      )*64 + c];
        else if (oc < 16) v = Wk[(oc -  8)*64 + c];
        else if (oc < 56) v = Wv[(oc - 16)*64 + c];
        else              v = Wc[(oc - 56)*64 + c];
        Wsm[c*96 + oc] = v;
    }
    // ---- load buffer slice Bs[c][v*64+w] (float4, coalesced) ----
    for (int f = t; f < 5120; f += 512) {
        int r  = f >> 4;          // c*5 + v
        int w4 = f & 15;
        int c = r / 5, v = r % 5;
        float4 val = *(const float4*)(buffer + (((size_t)(b*64 + c)*5 + v)*4096 + h*64 + w4*4));
        *(float4*)(Bs + c*320 + v*64 + w4*4) = val;
    }
    __syncthreads();

    // ---- Phase A: [96 x 64] x [64 x 320]: Q,K,V to smem, Wc-out to g_X ----
    {
        const int ocb = wid * 6;              // 16 warps * 6 oc = 96
        float acc[6][10];
        #pragma unroll
        for (int i = 0; i < 6; i++)
            #pragma unroll
            for (int j = 0; j < 10; j++) acc[i][j] = 0.f;

        for (int c = 0; c < 64; c++) {
            float wr[6];
            #pragma unroll
            for (int i = 0; i < 6; i++) wr[i] = Wsm[c*96 + ocb + i];
            #pragma unroll
            for (int j = 0; j < 10; j++) {
                float bv = Bs[c*320 + lane + 32*j];
                #pragma unroll
                for (int i = 0; i < 6; i++) acc[i][j] += wr[i]*bv;
            }
        }
        #pragma unroll
        for (int i = 0; i < 6; i++) {
            int oc = ocb + i;
            #pragma unroll
            for (int j = 0; j < 10; j++) {
                int n = lane + 32*j;
                if (oc < 56) {
                    QKV[oc*320 + n] = acc[i][j];
                } else {
                    int cc = oc - 56;                    // attention out-channel = c8*5 + ar
                    int c8 = cc / 5, ar = cc % 5;
                    int v = n >> 6, w = n & 63;
                    g_X[((((size_t)b*40 + c8*5 + v)*5 + ar)*64 + h)*64 + w] = acc[i][j];
                }
            }
        }
    }
    __syncthreads();

    // ---- Phase B: 5 tiles of 64 rows ----
    for (int tile = 0; tile < 5; tile++) {
        const int m0 = tile * 64;

        // B1: scores (inner dim 8) + softmax -> Ps (unnormalized exp), rinv
        {
            float q[4][8];
            #pragma unroll
            for (int mi = 0; mi < 4; mi++)
                #pragma unroll
                for (int d = 0; d < 8; d++)
                    q[mi][d] = QKV[d*320 + m0 + wid*4 + mi];

            float s[4][10];
            #pragma unroll
            for (int j = 0; j < 10; j++) {
                int n = lane + 32*j;
                float kv[8];
                #pragma unroll
                for (int d = 0; d < 8; d++) kv[d] = QKV[(8+d)*320 + n];
                #pragma unroll
                for (int mi = 0; mi < 4; mi++) {
                    float a = 0.f;
                    #pragma unroll
                    for (int d = 0; d < 8; d++) a += q[mi][d]*kv[d];
                    s[mi][j] = a;
                }
            }
            #pragma unroll
            for (int mi = 0; mi < 4; mi++) {
                float mx = s[mi][0];
                #pragma unroll
                for (int j = 1; j < 10; j++) mx = fmaxf(mx, s[mi][j]);
                #pragma unroll
                for (int o = 16; o; o >>= 1) mx = fmaxf(mx, __shfl_xor_sync(0xffffffffu, mx, o));
                float sum = 0.f;
                #pragma unroll
                for (int j = 0; j < 10; j++) { float e = __expf(s[mi][j] - mx); s[mi][j] = e; sum += e; }
                #pragma unroll
                for (int o = 16; o; o >>= 1) sum += __shfl_xor_sync(0xffffffffu, sum, o);
                int r = wid*4 + mi;
                #pragma unroll
                for (int j = 0; j < 10; j++) Ps[r*PS_STRIDE + lane + 32*j] = s[mi][j];
                if (lane == 0) rinv[r] = 1.0f / sum;
            }
        }
        __syncthreads();

        // B2: O[64][40] = P[64][320] * V^T ; subgroup of 8 lanes per row
        {
            const int sg = lane >> 3, l8 = lane & 7;
            const int r  = wid*4 + sg;          // tile-local row
            float acc[40];
            #pragma unroll
            for (int oc = 0; oc < 40; oc++) acc[oc] = 0.f;

            const float* prow = Ps + r*PS_STRIDE;
            const float* vbase = QKV + 16*320;
            for (int jj = 0; jj < 40; jj++) {
                int n = jj*8 + l8;
                float p = prow[n];
                const float* vp = vbase + n;
                #pragma unroll
                for (int oc = 0; oc < 40; oc++) acc[oc] += p * vp[oc*320];
            }
            #pragma unroll
            for (int oc = 0; oc < 40; oc++) {
                float a = acc[oc];
                a += __shfl_xor_sync(0xffffffffu, a, 1);
                a += __shfl_xor_sync(0xffffffffu, a, 2);
                a += __shfl_xor_sync(0xffffffffu, a, 4);
                acc[oc] = a;
            }
            float scale = rinv[r];
            int m_g = m0 + r;
            int v = m_g >> 6, w = m_g & 63;
            // lane l8 writes oc = l8*5 + q2  ->  c8 = l8, ar = q2
            #pragma unroll
            for (int q2 = 0; q2 < 5; q2++) {
                int oc = l8*5 + q2;
                size_t idx = ((((size_t)b*40 + l8*5 + v)*5 + q2)*64 + h)*64 + w;
                g_X[idx] += scale * acc[oc];
            }
        }
        __syncthreads();
    }
}

// ---------------- conv1: [64oc] x [40ci x 7kw] over W, + ReLU ----------------
#define C1_WS_OFF 2880                       // Xs[40][72]
#define C1_SMEM_FLOATS (C1_WS_OFF + 280*65)  // 21080
#define C1_SMEM_BYTES  (C1_SMEM_FLOATS*4)

__global__ __launch_bounds__(256)
void conv1_kernel(const float* __restrict__ W1)
{
    extern __shared__ float sm[];
    float* Xs = sm;               // [ci][72], data at [ci][3+w], pads zeroed
    float* Ws = sm + C1_WS_OFF;   // [(ci*7+kw)*65 + oc]
    const int h = blockIdx.x, d = blockIdx.y, b = blockIdx.z;
    const int t = threadIdx.x, lane = t & 31;
    const int ocb = (t >> 5) * 8;

    // zero pad columns only (indices 0..2 and 64+3..64+5 -> 67..69)
    for (int idx = t; idx < 240; idx += 256) {
        int ci = idx / 6, p = idx % 6;
        Xs[ci*72 + (p < 3 ? p : 64 + p)] = 0.f;
    }
    // fill X rows
    for (int idx = t; idx < 40*64; idx += 256) {
        int ci = idx >> 6, w = idx & 63;
        Xs[ci*72 + 3 + w] = g_X[(((size_t)b*40 + ci)*5 + d)*4096 + h*64 + w];
    }
    // weights: LDG-coalesced, STS conflict-free (stride 65)
    for (int idx = t; idx < 64*280; idx += 256) {
        int oc = idx / 280, r = idx % 280;
        Ws[r*65 + oc] = W1[idx];
    }
    __syncthreads();

    float acc0[8], acc1[8];
    #pragma unroll
    for (int i = 0; i < 8; i++) { acc0[i] = 0.f; acc1[i] = 0.f; }

    for (int ci = 0; ci < 40; ci++) {
        #pragma unroll
        for (int kw = 0; kw < 7; kw++) {
            float x0 = Xs[ci*72 + lane + kw];
            float x1 = Xs[ci*72 + 32 + lane + kw];
            const float* wp = Ws + (ci*7+kw)*65 + ocb;
            #pragma unroll
            for (int i = 0; i < 8; i++) { float wv = wp[i]; acc0[i] += wv*x0; acc1[i] += wv*x1; }
        }
    }
    size_t obase = (((size_t)b*64 + ocb)*5 + d)*4096 + h*64;
    #pragma unroll
    for (int i = 0; i < 8; i++) {
        g_Y1[obase + (size_t)i*5*4096 + lane]      = fmaxf(acc0[i], 0.f);
        g_Y1[obase + (size_t)i*5*4096 + 32 + lane] = fmaxf(acc1[i], 0.f);
    }
}

// ---------------- conv2: [64oc] x [64c x 7kd] over D(=5), + ReLU ----------------
#define C2_WS_OFF 20480                       // Ys[64][5][64]
#define C2_SMEM_FLOATS (C2_WS_OFF + 448*65)   // 49600
#define C2_SMEM_BYTES  (C2_SMEM_FLOATS*4)

__global__ __launch_bounds__(512)
void conv2_kernel(const float* __restrict__ W2, float* __restrict__ out)
{
    extern __shared__ float sm[];
    float* Ys = sm;               // [(c*5+d)*64 + w]
    float* Ws = sm + C2_WS_OFF;   // [(c*7+kd)*65 + oc]
    const int h = blockIdx.x, b = blockIdx.y;
    const int t = threadIdx.x;
    const int oc = t >> 3, wg = t & 7;

    for (int f = t; f < 5120; f += 512) {
        int r = f >> 4, w4 = f & 15;
        int c = r / 5, d = r % 5;
        *(float4*)(Ys + r*64 + w4*4) =
            *(const float4*)(g_Y1 + (((size_t)b*64 + c)*5 + d)*4096 + h*64 + w4*4);
    }
    for (int idx = t; idx < 64*448; idx += 512) {
        int o = idx / 448, r = idx % 448;
        Ws[r*65 + o] = W2[idx];
    }
    __syncthreads();

    float acc[5][8];
    #pragma unroll
    for (int d = 0; d < 5; d++)
        #pragma unroll
        for (int j = 0; j < 8; j++) acc[d][j] = 0.f;

    for (int c = 0; c < 64; c++) {
        float wr[7];
        #pragma unroll
        for (int kd = 0; kd < 7; kd++) wr[kd] = Ws[(c*7+kd)*65 + oc];
        #pragma unroll
        for (int dp = 0; dp < 5; dp++) {
            const float* yp = Ys + (c*5+dp)*64 + wg*8;
            float4 ya = *(const float4*)yp;
            float4 yb = *(const float4*)(yp + 4);
            float y[8] = {ya.x, ya.y, ya.z, ya.w, yb.x, yb.y, yb.z, yb.w};
            #pragma unroll
            for (int d = 0; d < 5; d++) {
                int kd = dp - d + 3;
                if (kd < 0 || kd > 6) continue;     // compile-time pruned
                float wv = wr[kd];
                #pragma unroll
                for (int j = 0; j < 8; j++) acc[d][j] += wv*y[j];
            }
        }
    }
    #pragma unroll
    for (int d = 0; d < 5; d++) {
        size_t idx = (((size_t)b*64 + oc)*5 + d)*4096 + h*64 + wg*8;
        float4 o0, o1;
        o0.x = fmaxf(acc[d][0], 0.f); o0.y = fmaxf(acc[d][1], 0.f);
        o0.z = fmaxf(acc[d][2], 0.f); o0.w = fmaxf(acc[d][3], 0.f);
        o1.x = fmaxf(acc[d][4], 0.f); o1.y = fmaxf(acc[d][5], 0.f);
        o1.z = fmaxf(acc[d][6], 0.f); o1.w = fmaxf(acc[d][7], 0.f);
        *(float4*)(out + idx)     = o0;
        *(float4*)(out + idx + 4) = o1;
    }
}

// ---------------- launch ----------------
extern "C" void kernel_launch(void* const* d_in, const int* in_sizes, int n_in,
                              void* d_out, int out_size)
{
    const float* buffer = (const float*)d_in[0];
    const float* Wq = (const float*)d_in[1];
    const float* Wk = (const float*)d_in[2];
    const float* Wv = (const float*)d_in[3];
    const float* Wc = (const float*)d_in[4];
    const float* W1 = (const float*)d_in[5];
    const float* W2 = (const float*)d_in[6];
    float* out = (float*)d_out;

    cudaFuncSetAttribute(attn_kernel,  cudaFuncAttributeMaxDynamicSharedMemorySize, ATTN_SMEM_BYTES);
    cudaFuncSetAttribute(conv1_kernel, cudaFuncAttributeMaxDynamicSharedMemorySize, C1_SMEM_BYTES);
    cudaFuncSetAttribute(conv2_kernel, cudaFuncAttributeMaxDynamicSharedMemorySize, C2_SMEM_BYTES);

    attn_kernel <<<dim3(64, 8),    512, ATTN_SMEM_BYTES>>>(buffer, Wq, Wk, Wv, Wc);
    conv1_kernel<<<dim3(64, 5, 8), 256, C1_SMEM_BYTES>>>(W1);
    conv2_kernel<<<dim3(64, 8),    512, C2_SMEM_BYTES>>>(W2, out);
}